// round 1
// baseline (speedup 1.0000x reference)
#include <cuda_runtime.h>
#include <cuda_bf16.h>
#include <math.h>

#define QLEN 1024
#define BATCH 4
#define DMODEL 512
#define HEADS 8
#define DHEAD 64
#define MEMLEN 1024
#define KLEN 2048
#define DMLP 2048
#define BH 32            // BATCH*HEADS
#define QROWS (QLEN*BATCH)   // 4096
#define KROWS (KLEN*BATCH)   // 8192
#define QKVW (3*DMODEL)      // 1536
#define QKVROWSTRIDE (BATCH*QKVW) // 6144

// ---------------- scratch (__device__ globals; no allocations allowed) -------
__device__ float g_cat[KLEN*BATCH*DMODEL];          // 16MB
__device__ float g_qkv[KLEN*BATCH*QKVW];            // 48MB
__device__ float g_rk[KLEN*DMODEL];                 // 4MB
__device__ float g_AC[(size_t)BH*QLEN*KLEN];        // 256MB (reused as prob)
__device__ float g_BD[(size_t)BH*QLEN*KLEN];        // 256MB
__device__ float g_attn[QROWS*DMODEL];              // 8MB
__device__ float g_ao[QROWS*DMODEL];                // 8MB
__device__ float g_y[QROWS*DMODEL];                 // 8MB
__device__ float g_h[QROWS*DMLP];                   // 32MB
__device__ float g_z[QROWS*DMODEL];                 // 8MB

// ---------------- generic fp32 GEMM: C[M,N] = A[M,K] @ W[N,K]^T (+bias,+relu)
// M,N multiples of 64. act: 0=none 1=bias 2=bias+relu
__global__ void gemm_nt(const float* __restrict__ A, const float* __restrict__ W,
                        const float* __restrict__ bias, float* __restrict__ C,
                        int M, int N, int K, int act) {
    __shared__ float As[64][33];
    __shared__ float Ws[64][33];
    const int tid = threadIdx.x;
    const int tx = tid & 15, ty = tid >> 4;
    const int i0 = blockIdx.y * 64, n0 = blockIdx.x * 64;
    float acc[4][4] = {};
    for (int kt = 0; kt < K; kt += 32) {
        #pragma unroll
        for (int l = 0; l < 8; l++) {
            int e = l * 256 + tid;
            int r = e >> 5, c = e & 31;
            As[r][c] = A[(size_t)(i0 + r) * K + kt + c];
            Ws[r][c] = W[(size_t)(n0 + r) * K + kt + c];
        }
        __syncthreads();
        #pragma unroll
        for (int kk = 0; kk < 32; kk++) {
            float a[4], w[4];
            #pragma unroll
            for (int r = 0; r < 4; r++) a[r] = As[ty * 4 + r][kk];
            #pragma unroll
            for (int c = 0; c < 4; c++) w[c] = Ws[c * 16 + tx][kk];
            #pragma unroll
            for (int r = 0; r < 4; r++)
                #pragma unroll
                for (int c = 0; c < 4; c++)
                    acc[r][c] += a[r] * w[c];
        }
        __syncthreads();
    }
    #pragma unroll
    for (int r = 0; r < 4; r++) {
        int i = i0 + ty * 4 + r;
        #pragma unroll
        for (int c = 0; c < 4; c++) {
            int n = n0 + c * 16 + tx;
            float val = acc[r][c];
            if (act >= 1) val += bias[n];
            if (act == 2) val = fmaxf(val, 0.0f);
            C[(size_t)i * N + n] = val;
        }
    }
}

// ---------------- AC scores: AC[bh][i][j] = sum_d (q[i]+u)·k[j] --------------
__global__ void ac_kernel(const float* __restrict__ qkv, const float* __restrict__ u,
                          float* __restrict__ AC) {
    const int bh = blockIdx.z, b = bh >> 3, h = bh & 7;
    const int i0 = blockIdx.y * 64, j0 = blockIdx.x * 64;
    if (j0 > i0 + 63 + MEMLEN) return;   // fully-masked tile
    __shared__ float Qs[64][65];
    __shared__ float Ks[64][65];
    const int tid = threadIdx.x, tx = tid & 15, ty = tid >> 4;
    const float* qbase = qkv + (size_t)MEMLEN * QKVROWSTRIDE + b * QKVW + h * DHEAD;
    const float* kbase = qkv + b * QKVW + DMODEL + h * DHEAD;
    #pragma unroll
    for (int l = 0; l < 16; l++) {
        int e = l * 256 + tid;
        int r = e >> 6, d = e & 63;
        Qs[r][d] = qbase[(size_t)(i0 + r) * QKVROWSTRIDE + d] + u[h * DHEAD + d];
        Ks[r][d] = kbase[(size_t)(j0 + r) * QKVROWSTRIDE + d];
    }
    __syncthreads();
    float acc[4][4] = {};
    #pragma unroll
    for (int kk = 0; kk < 64; kk++) {
        float a[4], w[4];
        #pragma unroll
        for (int r = 0; r < 4; r++) a[r] = Qs[ty * 4 + r][kk];
        #pragma unroll
        for (int c = 0; c < 4; c++) w[c] = Ks[c * 16 + tx][kk];
        #pragma unroll
        for (int r = 0; r < 4; r++)
            #pragma unroll
            for (int c = 0; c < 4; c++)
                acc[r][c] += a[r] * w[c];
    }
    float* out = AC + (size_t)bh * QLEN * KLEN;
    #pragma unroll
    for (int r = 0; r < 4; r++)
        #pragma unroll
        for (int c = 0; c < 4; c++)
            out[(size_t)(i0 + ty * 4 + r) * KLEN + j0 + c * 16 + tx] = acc[r][c];
}

// ---------------- BD raw scores: BD[bh][i][p] = sum_d (q[i]+v)·rk[p] ---------
__global__ void bd_kernel(const float* __restrict__ qkv, const float* __restrict__ v,
                          const float* __restrict__ rk, float* __restrict__ BD) {
    const int bh = blockIdx.z, b = bh >> 3, h = bh & 7;
    const int i0 = blockIdx.y * 64, p0 = blockIdx.x * 64;
    if (p0 + i0 < 897) return;  // min needed p for this i-tile is 960-i0; tile max p0+63
    __shared__ float Qs[64][65];
    __shared__ float Rs[64][65];
    const int tid = threadIdx.x, tx = tid & 15, ty = tid >> 4;
    const float* qbase = qkv + (size_t)MEMLEN * QKVROWSTRIDE + b * QKVW + h * DHEAD;
    const float* rbase = rk + h * DHEAD;
    #pragma unroll
    for (int l = 0; l < 16; l++) {
        int e = l * 256 + tid;
        int r = e >> 6, d = e & 63;
        Qs[r][d] = qbase[(size_t)(i0 + r) * QKVROWSTRIDE + d] + v[h * DHEAD + d];
        Rs[r][d] = rbase[(size_t)(p0 + r) * DMODEL + d];
    }
    __syncthreads();
    float acc[4][4] = {};
    #pragma unroll
    for (int kk = 0; kk < 64; kk++) {
        float a[4], w[4];
        #pragma unroll
        for (int r = 0; r < 4; r++) a[r] = Qs[ty * 4 + r][kk];
        #pragma unroll
        for (int c = 0; c < 4; c++) w[c] = Rs[c * 16 + tx][kk];
        #pragma unroll
        for (int r = 0; r < 4; r++)
            #pragma unroll
            for (int c = 0; c < 4; c++)
                acc[r][c] += a[r] * w[c];
    }
    float* out = BD + (size_t)bh * QLEN * KLEN;
    #pragma unroll
    for (int r = 0; r < 4; r++)
        #pragma unroll
        for (int c = 0; c < 4; c++)
            out[(size_t)(i0 + ty * 4 + r) * KLEN + p0 + c * 16 + tx] = acc[r][c];
}

// ---------------- softmax with rel_shift gather; writes prob into P=[bh,i,j] -
// score[i,j] = (AC[i,j] + BD[i, j-i+1023]) * 0.125 for j<=i+MEM, else -1e30
__global__ void softmax_kernel(const float* __restrict__ AC, const float* __restrict__ BD,
                               float* __restrict__ P) {
    const int i = blockIdx.x, bh = blockIdx.y;
    __shared__ float s[KLEN];
    __shared__ float red[256];
    const int tid = threadIdx.x;
    const size_t rowoff = (size_t)bh * QLEN * KLEN + (size_t)i * KLEN;
    const float* ac = AC + rowoff;
    const float* bd = BD + rowoff + (QLEN - 1 - i);   // p = j - i + 1023
    const int jmax = i + MEMLEN;                       // inclusive last valid j
    for (int j = tid; j < KLEN; j += 256)
        s[j] = (j <= jmax) ? (ac[j] + bd[j]) * 0.125f : -1e30f;
    __syncthreads();
    float m = -1e30f;
    for (int j = tid; j < KLEN; j += 256) m = fmaxf(m, s[j]);
    red[tid] = m; __syncthreads();
    for (int o = 128; o > 0; o >>= 1) {
        if (tid < o) red[tid] = fmaxf(red[tid], red[tid + o]);
        __syncthreads();
    }
    m = red[0]; __syncthreads();
    float sum = 0.0f;
    for (int j = tid; j < KLEN; j += 256) {
        float e = __expf(s[j] - m);
        s[j] = e;
        sum += e;
    }
    red[tid] = sum; __syncthreads();
    for (int o = 128; o > 0; o >>= 1) {
        if (tid < o) red[tid] += red[tid + o];
        __syncthreads();
    }
    const float inv = 1.0f / red[0];
    float* pout = P + rowoff;
    for (int j = tid; j < KLEN; j += 256) pout[j] = s[j] * inv;
}

// ---------------- transpose P[bh,i,j] -> out[i,j,bh] (prob output layout) ----
__global__ void transpose_prob(const float* __restrict__ P, float* __restrict__ out) {
    __shared__ float t[32][33];
    const int i = blockIdx.y, j0 = blockIdx.x * 32;
    const int tid = threadIdx.x;
    const int lj = tid & 31, lb = tid >> 5;
    #pragma unroll
    for (int r = 0; r < 4; r++) {
        int bh = r * 8 + lb;
        t[lj][bh] = P[((size_t)bh * QLEN + i) * KLEN + j0 + lj];
    }
    __syncthreads();
    const int lbh = tid & 31, ljw = tid >> 5;
    #pragma unroll
    for (int r = 0; r < 4; r++) {
        int jj = r * 8 + ljw;
        out[((size_t)i * KLEN + j0 + jj) * 32 + lbh] = t[jj][lbh];
    }
}

// ---------------- attn[i, b, h*64+d] = sum_j P[bh][i][j] * V[j,b,h,d] --------
__global__ void attn_kernel(const float* __restrict__ P, const float* __restrict__ qkv,
                            float* __restrict__ attn) {
    const int bh = blockIdx.z, b = bh >> 3, h = bh & 7;
    const int i0 = blockIdx.y * 64;
    __shared__ float Ps[64][65];
    __shared__ float Vs[64][65];
    const int tid = threadIdx.x, tx = tid & 15, ty = tid >> 4;
    const float* prow = P + (size_t)bh * QLEN * KLEN + (size_t)i0 * KLEN;
    const float* vbase = qkv + b * QKVW + 2 * DMODEL + h * DHEAD;
    const int jend = i0 + 64 + MEMLEN;   // first fully-zero chunk boundary (<= KLEN)
    float acc[4][4] = {};
    for (int jc = 0; jc < jend && jc < KLEN; jc += 64) {
        #pragma unroll
        for (int l = 0; l < 16; l++) {
            int e = l * 256 + tid;
            int r = e >> 6, c = e & 63;
            Ps[r][c] = prow[(size_t)r * KLEN + jc + c];
            Vs[r][c] = vbase[(size_t)(jc + r) * QKVROWSTRIDE + c];
        }
        __syncthreads();
        #pragma unroll
        for (int kk = 0; kk < 64; kk++) {
            float a[4], w[4];
            #pragma unroll
            for (int r = 0; r < 4; r++) a[r] = Ps[ty * 4 + r][kk];
            #pragma unroll
            for (int c = 0; c < 4; c++) w[c] = Vs[kk][c * 16 + tx];
            #pragma unroll
            for (int r = 0; r < 4; r++)
                #pragma unroll
                for (int c = 0; c < 4; c++)
                    acc[r][c] += a[r] * w[c];
        }
        __syncthreads();
    }
    #pragma unroll
    for (int r = 0; r < 4; r++) {
        int i = i0 + ty * 4 + r;
        #pragma unroll
        for (int c = 0; c < 4; c++) {
            int d = c * 16 + tx;
            attn[((size_t)i * BATCH + b) * DMODEL + h * DHEAD + d] = acc[r][c];
        }
    }
}

// ---------------- residual add + layernorm (row length 512) ------------------
__global__ void add_ln(const float* __restrict__ x1, const float* __restrict__ x2,
                       const float* __restrict__ g, const float* __restrict__ bb,
                       float* __restrict__ out) {
    const int row = blockIdx.x;
    const int tid = threadIdx.x;   // 256 threads, 2 elems each
    __shared__ float red[256];
    __shared__ float red2[256];
    const float* a = x1 + (size_t)row * DMODEL;
    const float* c = x2 + (size_t)row * DMODEL;
    float v0 = a[tid] + c[tid];
    float v1 = a[tid + 256] + c[tid + 256];
    red[tid] = v0 + v1;
    red2[tid] = v0 * v0 + v1 * v1;
    __syncthreads();
    for (int o = 128; o > 0; o >>= 1) {
        if (tid < o) { red[tid] += red[tid + o]; red2[tid] += red2[tid + o]; }
        __syncthreads();
    }
    const float mu = red[0] * (1.0f / DMODEL);
    const float var = red2[0] * (1.0f / DMODEL) - mu * mu;
    const float rstd = rsqrtf(var + 1e-5f);
    float* o = out + (size_t)row * DMODEL;
    o[tid]       = (v0 - mu) * rstd * g[tid]       + bb[tid];
    o[tid + 256] = (v1 - mu) * rstd * g[tid + 256] + bb[tid + 256];
}

// ---------------- launch ----------------
extern "C" void kernel_launch(void* const* d_in, const int* in_sizes, int n_in,
                              void* d_out, int out_size) {
    const float* inputs = (const float*)d_in[0];
    const float* r      = (const float*)d_in[1];
    const float* u      = (const float*)d_in[2];
    const float* v      = (const float*)d_in[3];
    const float* mem    = (const float*)d_in[4];
    // d_in[5] = attn_mask (deterministic function of indices; computed inline)
    const float* Wqkv   = (const float*)d_in[6];
    const float* Wr     = (const float*)d_in[7];
    const float* Wo     = (const float*)d_in[8];
    const float* ln1_g  = (const float*)d_in[9];
    const float* ln1_b  = (const float*)d_in[10];
    const float* w1     = (const float*)d_in[11];
    const float* b1     = (const float*)d_in[12];
    const float* w2     = (const float*)d_in[13];
    const float* b2     = (const float*)d_in[14];
    const float* ln2_g  = (const float*)d_in[15];
    const float* ln2_b  = (const float*)d_in[16];

    float *catp, *qkvp, *rkp, *acp, *bdp, *attnp, *aop, *yp, *hp, *zp;
    cudaGetSymbolAddress((void**)&catp,  g_cat);
    cudaGetSymbolAddress((void**)&qkvp,  g_qkv);
    cudaGetSymbolAddress((void**)&rkp,   g_rk);
    cudaGetSymbolAddress((void**)&acp,   g_AC);
    cudaGetSymbolAddress((void**)&bdp,   g_BD);
    cudaGetSymbolAddress((void**)&attnp, g_attn);
    cudaGetSymbolAddress((void**)&aop,   g_ao);
    cudaGetSymbolAddress((void**)&yp,    g_y);
    cudaGetSymbolAddress((void**)&hp,    g_h);
    cudaGetSymbolAddress((void**)&zp,    g_z);

    // 1. cat = concat(mem, inputs) along klen
    cudaMemcpyAsync(catp, mem, (size_t)MEMLEN * BATCH * DMODEL * sizeof(float),
                    cudaMemcpyDeviceToDevice, 0);
    cudaMemcpyAsync(catp + (size_t)MEMLEN * BATCH * DMODEL, inputs,
                    (size_t)QLEN * BATCH * DMODEL * sizeof(float),
                    cudaMemcpyDeviceToDevice, 0);

    // 2. qkv = cat @ Wqkv^T   [8192, 1536]
    gemm_nt<<<dim3(QKVW / 64, KROWS / 64), 256>>>(catp, Wqkv, nullptr, qkvp,
                                                  KROWS, QKVW, DMODEL, 0);
    // 3. rk = r @ Wr^T        [2048, 512]
    gemm_nt<<<dim3(DMODEL / 64, KLEN / 64), 256>>>(r, Wr, nullptr, rkp,
                                                   KLEN, DMODEL, DMODEL, 0);
    // 4-5. scores
    ac_kernel<<<dim3(KLEN / 64, QLEN / 64, BH), 256>>>(qkvp, u, acp);
    bd_kernel<<<dim3(KLEN / 64, QLEN / 64, BH), 256>>>(qkvp, v, rkp, bdp);
    // 6. softmax (in-place into AC buffer = prob [bh,i,j])
    softmax_kernel<<<dim3(QLEN, BH), 256>>>(acp, bdp, acp);
    // 7. prob output (tuple layout: out [qlen,b,d] first, then prob [q,k,b,h])
    if (out_size == QLEN * BATCH * DMODEL + (size_t)QLEN * KLEN * BH) {
        float* prob_out = (float*)d_out + QLEN * BATCH * DMODEL;
        transpose_prob<<<dim3(KLEN / 32, QLEN), 256>>>(acp, prob_out);
    }
    // 8. attn = prob @ V
    attn_kernel<<<dim3(1, QLEN / 64, BH), 256>>>(acp, qkvp, attnp);
    // 9. attn_out = attn @ Wo^T
    gemm_nt<<<dim3(DMODEL / 64, QROWS / 64), 256>>>(attnp, Wo, nullptr, aop,
                                                    QROWS, DMODEL, DMODEL, 0);
    // 10. y = LN1(inputs + attn_out)
    add_ln<<<QROWS, 256>>>(inputs, aop, ln1_g, ln1_b, yp);
    // 11. h = relu(y @ w1^T + b1)
    gemm_nt<<<dim3(DMLP / 64, QROWS / 64), 256>>>(yp, w1, b1, hp,
                                                  QROWS, DMLP, DMODEL, 2);
    // 12. z = h @ w2^T + b2
    gemm_nt<<<dim3(DMODEL / 64, QROWS / 64), 256>>>(hp, w2, b2, zp,
                                                    QROWS, DMODEL, DMLP, 1);
    // 13. out = LN2(y + z)
    add_ln<<<QROWS, 256>>>(yp, zp, ln2_g, ln2_b, (float*)d_out);
}

// round 2
// speedup vs baseline: 1.8515x; 1.8515x over previous
#include <cuda_runtime.h>
#include <math.h>

#define QLEN 1024
#define BATCH 4
#define DMODEL 512
#define HEADS 8
#define DHEAD 64
#define MEMLEN 1024
#define KLEN 2048
#define DMLP 2048
#define BH 32
#define QROWS 4096
#define KROWS 8192
#define QKVW 1536
#define QSTRIDE 6144                 // qkv floats per j (4 batches * 1536)
#define QK ((size_t)QLEN * KLEN)

// ---------------- scratch ----------------
__device__ float g_qkv[KROWS * QKVW];            // 48MB
__device__ float g_rk[KLEN * DMODEL];            // 4MB
__device__ float g_qu[BH * QLEN * DHEAD];        // 8MB
__device__ float g_qv[BH * QLEN * DHEAD];        // 8MB
__device__ float g_vt[BH * DHEAD * KLEN];        // 16MB  Vt[bh][d][j]
__device__ float g_S[(size_t)BH * QLEN * KLEN];  // 256MB (scores -> prob)
__device__ float g_BD[(size_t)BH * QLEN * KLEN]; // 256MB
__device__ float g_attn[QROWS * DMODEL];
__device__ float g_ao[QROWS * DMODEL];
__device__ float g_y[QROWS * DMODEL];
__device__ float g_h[QROWS * DMLP];
__device__ float g_z[QROWS * DMODEL];

// ---------------- tf32 helpers ----------------
__device__ __forceinline__ float f2tf(float x) {
    unsigned r;
    asm("cvt.rna.tf32.f32 %0, %1;" : "=r"(r) : "f"(x));
    return __uint_as_float(r);
}

// Generic NT tile: C[BMxBN] += A[BMxK] @ B[BNxK]^T, tf32 tensor cores.
// A,B,C,bias pre-offset to tile origin by caller. K0..K1 multiple of 16.
template<int BM, int BN, int WM, int WN>
__device__ __forceinline__ void gemm_tile(
    const float* __restrict__ A, int lda,
    const float* __restrict__ B, int ldb,
    float* __restrict__ C, int ldc,
    int K0, int K1, const float* __restrict__ bias, int act)
{
    constexpr int WARPS_M = BM / WM;
    constexpr int WARPS_N = BN / WN;
    constexpr int NTH = WARPS_M * WARPS_N * 32;
    constexpr int MT = WM / 16;
    constexpr int NT = WN / 8;
    __shared__ float As[BM][20];
    __shared__ float Bs[BN][20];
    const int tid = threadIdx.x;
    const int lane = tid & 31;
    const int warp = tid >> 5;
    const int wm = warp % WARPS_M;
    const int wn = warp / WARPS_M;
    const int grp = lane >> 2, tig = lane & 3;

    float acc[MT][NT][4];
    #pragma unroll
    for (int mt = 0; mt < MT; mt++)
        #pragma unroll
        for (int nt = 0; nt < NT; nt++)
            #pragma unroll
            for (int q = 0; q < 4; q++) acc[mt][nt][q] = 0.0f;

    for (int kt = K0; kt < K1; kt += 16) {
        #pragma unroll
        for (int l = 0; l < (BM * 4) / NTH; l++) {
            int idx = l * NTH + tid;
            int r = idx >> 2, c = (idx & 3) << 2;
            float4 v = *(const float4*)(A + (size_t)r * lda + kt + c);
            As[r][c]     = f2tf(v.x);
            As[r][c + 1] = f2tf(v.y);
            As[r][c + 2] = f2tf(v.z);
            As[r][c + 3] = f2tf(v.w);
        }
        #pragma unroll
        for (int l = 0; l < (BN * 4) / NTH; l++) {
            int idx = l * NTH + tid;
            int r = idx >> 2, c = (idx & 3) << 2;
            float4 v = *(const float4*)(B + (size_t)r * ldb + kt + c);
            Bs[r][c]     = f2tf(v.x);
            Bs[r][c + 1] = f2tf(v.y);
            Bs[r][c + 2] = f2tf(v.z);
            Bs[r][c + 3] = f2tf(v.w);
        }
        __syncthreads();
        #pragma unroll
        for (int ks = 0; ks < 16; ks += 8) {
            unsigned af[MT][4], bf[NT][2];
            #pragma unroll
            for (int mt = 0; mt < MT; mt++) {
                int rowb = wm * WM + mt * 16;
                af[mt][0] = __float_as_uint(As[rowb + grp][ks + tig]);
                af[mt][1] = __float_as_uint(As[rowb + grp + 8][ks + tig]);
                af[mt][2] = __float_as_uint(As[rowb + grp][ks + tig + 4]);
                af[mt][3] = __float_as_uint(As[rowb + grp + 8][ks + tig + 4]);
            }
            #pragma unroll
            for (int nt = 0; nt < NT; nt++) {
                int colb = wn * WN + nt * 8 + grp;
                bf[nt][0] = __float_as_uint(Bs[colb][ks + tig]);
                bf[nt][1] = __float_as_uint(Bs[colb][ks + tig + 4]);
            }
            #pragma unroll
            for (int mt = 0; mt < MT; mt++)
                #pragma unroll
                for (int nt = 0; nt < NT; nt++)
                    asm volatile(
                        "mma.sync.aligned.m16n8k8.row.col.f32.tf32.tf32.f32 "
                        "{%0,%1,%2,%3}, {%4,%5,%6,%7}, {%8,%9}, {%0,%1,%2,%3};"
                        : "+f"(acc[mt][nt][0]), "+f"(acc[mt][nt][1]),
                          "+f"(acc[mt][nt][2]), "+f"(acc[mt][nt][3])
                        : "r"(af[mt][0]), "r"(af[mt][1]), "r"(af[mt][2]), "r"(af[mt][3]),
                          "r"(bf[nt][0]), "r"(bf[nt][1]));
        }
        __syncthreads();
    }

    #pragma unroll
    for (int mt = 0; mt < MT; mt++) {
        int r0 = wm * WM + mt * 16 + grp;
        #pragma unroll
        for (int nt = 0; nt < NT; nt++) {
            int c0 = wn * WN + nt * 8 + tig * 2;
            float v0 = acc[mt][nt][0], v1 = acc[mt][nt][1];
            float v2 = acc[mt][nt][2], v3 = acc[mt][nt][3];
            if (act >= 1) {
                float b0 = bias[c0], b1 = bias[c0 + 1];
                v0 += b0; v1 += b1; v2 += b0; v3 += b1;
            }
            if (act == 2) {
                v0 = fmaxf(v0, 0.f); v1 = fmaxf(v1, 0.f);
                v2 = fmaxf(v2, 0.f); v3 = fmaxf(v3, 0.f);
            }
            *(float2*)(C + (size_t)r0 * ldc + c0) = make_float2(v0, v1);
            *(float2*)(C + (size_t)(r0 + 8) * ldc + c0) = make_float2(v2, v3);
        }
    }
}

// ---------------- linear: C[M,N] = A[M,K] @ W[N,K]^T (+bias,+relu) ----------
__global__ __launch_bounds__(256, 2) void lin_gemm(
    const float* __restrict__ A, const float* __restrict__ W,
    const float* __restrict__ bias, float* __restrict__ C,
    int K, int N, int act)
{
    int m0 = blockIdx.y * 128, n0 = blockIdx.x * 128;
    gemm_tile<128, 128, 32, 64>(A + (size_t)m0 * K, K,
                                W + (size_t)n0 * K, K,
                                C + (size_t)m0 * N + n0, N,
                                0, K, bias ? bias + n0 : nullptr, act);
}

// ---------------- batched score GEMM (AC / BD) -------------------------------
// mode 0 (AC): B = K-part of qkv (strided); keep tile iff j0 - i0 <= 1024
// mode 1 (BD): B = rk (strided by head); keep tile iff j0 + i0 >= 896
__global__ __launch_bounds__(256, 2) void score_gemm(
    const float* __restrict__ Q, const float* __restrict__ Bbase,
    float* __restrict__ Out, int mode)
{
    int bh = blockIdx.z, b = bh >> 3, h = bh & 7;
    int i0 = blockIdx.y * 128, j0 = blockIdx.x * 128;
    if (mode == 0) { if (j0 - i0 > 1024) return; }
    else           { if (j0 + i0 < 896) return; }
    const float* A = Q + ((size_t)bh * QLEN + i0) * DHEAD;
    const float* Bp;
    int ldb;
    if (mode == 0) {
        Bp = Bbase + (size_t)j0 * QSTRIDE + b * QKVW + DMODEL + h * DHEAD;
        ldb = QSTRIDE;
    } else {
        Bp = Bbase + (size_t)j0 * DMODEL + h * DHEAD;
        ldb = DMODEL;
    }
    float* Cp = Out + (size_t)bh * QK + (size_t)i0 * KLEN + j0;
    gemm_tile<128, 128, 32, 64>(A, DHEAD, Bp, ldb, Cp, KLEN, 0, DHEAD, nullptr, 0);
}

// ---------------- attention: attn[i,b,h,d] = sum_j P[bh,i,j] Vt[bh,d,j] ------
__global__ __launch_bounds__(128) void attn_gemm(
    const float* __restrict__ P, const float* __restrict__ Vt,
    float* __restrict__ attn)
{
    int bh = blockIdx.y, b = bh >> 3, h = bh & 7;
    int i0 = blockIdx.x * 64;
    int K1 = min(KLEN, i0 + 64 + MEMLEN);
    gemm_tile<64, 64, 32, 32>(P + (size_t)bh * QK + (size_t)i0 * KLEN, KLEN,
                              Vt + (size_t)bh * DHEAD * KLEN, KLEN,
                              attn + (size_t)i0 * (BATCH * DMODEL) + b * DMODEL + h * DHEAD,
                              BATCH * DMODEL, 0, K1, nullptr, 0);
}

// ---------------- prep: Qu/Qv extraction -------------------------------------
__global__ void prep_quv(const float* __restrict__ qkv, const float* __restrict__ u,
                         const float* __restrict__ v, float* __restrict__ Qu,
                         float* __restrict__ Qv) {
    int i = blockIdx.x, b = blockIdx.y, t = threadIdx.x;   // 512 threads
    float q = qkv[(size_t)(MEMLEN + i) * QSTRIDE + b * QKVW + t];
    int h = t >> 6, d = t & 63;
    size_t o = ((size_t)(b * HEADS + h) * QLEN + i) * DHEAD + d;
    Qu[o] = q + u[t];
    Qv[o] = q + v[t];
}

// ---------------- prep: V transpose to Vt[bh][d][j] --------------------------
__global__ void prep_vt(const float* __restrict__ qkv, float* __restrict__ Vt) {
    __shared__ float t[32][33];
    int bh = blockIdx.z, b = bh >> 3, h = bh & 7;
    int j0 = blockIdx.x * 32, d0 = blockIdx.y * 32;
    int tc = threadIdx.x & 31, tr = threadIdx.x >> 5;   // 256 thr: 8 rows x 32 cols
    #pragma unroll
    for (int rr = 0; rr < 32; rr += 8)
        t[tr + rr][tc] = qkv[(size_t)(j0 + tr + rr) * QSTRIDE + b * QKVW
                             + 2 * DMODEL + h * DHEAD + d0 + tc];
    __syncthreads();
    #pragma unroll
    for (int rr = 0; rr < 32; rr += 8)
        Vt[((size_t)bh * DHEAD + d0 + tr + rr) * KLEN + j0 + tc] = t[tc][tr + rr];
}

// ---------------- softmax with rel_shift gather ------------------------------
__global__ void softmax_kernel(const float* __restrict__ AC, const float* __restrict__ BD,
                               float* __restrict__ P) {
    const int i = blockIdx.x, bh = blockIdx.y;
    __shared__ float s[KLEN];
    __shared__ float red[256];
    const int tid = threadIdx.x;
    const size_t rowoff = (size_t)bh * QK + (size_t)i * KLEN;
    const float* ac = AC + rowoff;
    const float* bd = BD + rowoff + (QLEN - 1 - i);   // p = j - i + 1023
    const int jmax = i + MEMLEN;
    for (int j = tid; j < KLEN; j += 256)
        s[j] = (j <= jmax) ? (ac[j] + bd[j]) * 0.125f : -1e30f;
    __syncthreads();
    float m = -1e30f;
    for (int j = tid; j < KLEN; j += 256) m = fmaxf(m, s[j]);
    red[tid] = m; __syncthreads();
    for (int o = 128; o > 0; o >>= 1) {
        if (tid < o) red[tid] = fmaxf(red[tid], red[tid + o]);
        __syncthreads();
    }
    m = red[0]; __syncthreads();
    float sum = 0.0f;
    for (int j = tid; j < KLEN; j += 256) {
        float e = __expf(s[j] - m);
        s[j] = e;
        sum += e;
    }
    red[tid] = sum; __syncthreads();
    for (int o = 128; o > 0; o >>= 1) {
        if (tid < o) red[tid] += red[tid + o];
        __syncthreads();
    }
    const float inv = 1.0f / red[0];
    float* pout = P + rowoff;
    for (int j = tid; j < KLEN; j += 256) pout[j] = s[j] * inv;
}

// ---------------- transpose P[bh,i,j] -> out[i,j,bh] --------------------------
__global__ void transpose_prob(const float* __restrict__ P, float* __restrict__ out) {
    __shared__ float t[32][33];
    const int i = blockIdx.y, j0 = blockIdx.x * 32;
    const int tid = threadIdx.x;
    const int lj = tid & 31, lb = tid >> 5;
    #pragma unroll
    for (int r = 0; r < 4; r++) {
        int bh = r * 8 + lb;
        t[lj][bh] = P[((size_t)bh * QLEN + i) * KLEN + j0 + lj];
    }
    __syncthreads();
    const int lbh = tid & 31, ljw = tid >> 5;
    #pragma unroll
    for (int r = 0; r < 4; r++) {
        int jj = r * 8 + ljw;
        out[((size_t)i * KLEN + j0 + jj) * 32 + lbh] = t[jj][lbh];
    }
}

// ---------------- residual add + layernorm -----------------------------------
__global__ void add_ln(const float* __restrict__ x1, const float* __restrict__ x2,
                       const float* __restrict__ g, const float* __restrict__ bb,
                       float* __restrict__ out) {
    const int row = blockIdx.x;
    const int tid = threadIdx.x;
    __shared__ float red[256];
    __shared__ float red2[256];
    const float* a = x1 + (size_t)row * DMODEL;
    const float* c = x2 + (size_t)row * DMODEL;
    float v0 = a[tid] + c[tid];
    float v1 = a[tid + 256] + c[tid + 256];
    red[tid] = v0 + v1;
    red2[tid] = v0 * v0 + v1 * v1;
    __syncthreads();
    for (int o = 128; o > 0; o >>= 1) {
        if (tid < o) { red[tid] += red[tid + o]; red2[tid] += red2[tid + o]; }
        __syncthreads();
    }
    const float mu = red[0] * (1.0f / DMODEL);
    const float var = red2[0] * (1.0f / DMODEL) - mu * mu;
    const float rstd = rsqrtf(var + 1e-5f);
    float* o = out + (size_t)row * DMODEL;
    o[tid]       = (v0 - mu) * rstd * g[tid]       + bb[tid];
    o[tid + 256] = (v1 - mu) * rstd * g[tid + 256] + bb[tid + 256];
}

// ---------------- launch ------------------------------------------------------
extern "C" void kernel_launch(void* const* d_in, const int* in_sizes, int n_in,
                              void* d_out, int out_size) {
    const float* inputs = (const float*)d_in[0];
    const float* r      = (const float*)d_in[1];
    const float* u      = (const float*)d_in[2];
    const float* v      = (const float*)d_in[3];
    const float* mem    = (const float*)d_in[4];
    const float* Wqkv   = (const float*)d_in[6];
    const float* Wr     = (const float*)d_in[7];
    const float* Wo     = (const float*)d_in[8];
    const float* ln1_g  = (const float*)d_in[9];
    const float* ln1_b  = (const float*)d_in[10];
    const float* w1     = (const float*)d_in[11];
    const float* b1     = (const float*)d_in[12];
    const float* w2     = (const float*)d_in[13];
    const float* b2     = (const float*)d_in[14];
    const float* ln2_g  = (const float*)d_in[15];
    const float* ln2_b  = (const float*)d_in[16];

    float *qkvp, *rkp, *qup, *qvp, *vtp, *sp, *bdp, *attnp, *aop, *yp, *hp, *zp;
    cudaGetSymbolAddress((void**)&qkvp,  g_qkv);
    cudaGetSymbolAddress((void**)&rkp,   g_rk);
    cudaGetSymbolAddress((void**)&qup,   g_qu);
    cudaGetSymbolAddress((void**)&qvp,   g_qv);
    cudaGetSymbolAddress((void**)&vtp,   g_vt);
    cudaGetSymbolAddress((void**)&sp,    g_S);
    cudaGetSymbolAddress((void**)&bdp,   g_BD);
    cudaGetSymbolAddress((void**)&attnp, g_attn);
    cudaGetSymbolAddress((void**)&aop,   g_ao);
    cudaGetSymbolAddress((void**)&yp,    g_y);
    cudaGetSymbolAddress((void**)&hp,    g_h);
    cudaGetSymbolAddress((void**)&zp,    g_z);

    // qkv = cat(mem, inputs) @ Wqkv^T  (two GEMMs, no concat copy)
    lin_gemm<<<dim3(QKVW / 128, 4096 / 128), 256>>>(mem, Wqkv, nullptr, qkvp,
                                                    DMODEL, QKVW, 0);
    lin_gemm<<<dim3(QKVW / 128, 4096 / 128), 256>>>(inputs, Wqkv, nullptr,
                                                    qkvp + (size_t)4096 * QKVW,
                                                    DMODEL, QKVW, 0);
    // rk = r @ Wr^T
    lin_gemm<<<dim3(DMODEL / 128, KLEN / 128), 256>>>(r, Wr, nullptr, rkp,
                                                      DMODEL, DMODEL, 0);
    // per-head extraction
    prep_quv<<<dim3(QLEN, BATCH), 512>>>(qkvp, u, v, qup, qvp);
    prep_vt<<<dim3(KLEN / 32, DHEAD / 32, BH), 256>>>(qkvp, vtp);
    // scores
    score_gemm<<<dim3(KLEN / 128, QLEN / 128, BH), 256>>>(qup, qkvp, sp, 0);
    score_gemm<<<dim3(KLEN / 128, QLEN / 128, BH), 256>>>(qvp, rkp, bdp, 1);
    // softmax (in-place into S => prob [bh,i,j])
    softmax_kernel<<<dim3(QLEN, BH), 256>>>(sp, bdp, sp);
    // prob output (tuple layout: out first, then prob [q,k,b,h])
    float* prob_out = (float*)d_out + QLEN * BATCH * DMODEL;
    transpose_prob<<<dim3(KLEN / 32, QLEN), 256>>>(sp, prob_out);
    // attn = prob @ V
    attn_gemm<<<dim3(QLEN / 64, BH), 128>>>(sp, vtp, attnp);
    // attn_out = attn @ Wo^T
    lin_gemm<<<dim3(DMODEL / 128, QROWS / 128), 256>>>(attnp, Wo, nullptr, aop,
                                                       DMODEL, DMODEL, 0);
    // y = LN1(inputs + attn_out)
    add_ln<<<QROWS, 256>>>(inputs, aop, ln1_g, ln1_b, yp);
    // MLP
    lin_gemm<<<dim3(DMLP / 128, QROWS / 128), 256>>>(yp, w1, b1, hp,
                                                     DMODEL, DMLP, 2);
    lin_gemm<<<dim3(DMODEL / 128, QROWS / 128), 256>>>(hp, w2, b2, zp,
                                                       DMLP, DMODEL, 1);
    // out = LN2(y + z)
    add_ln<<<QROWS, 256>>>(yp, zp, ln2_g, ln2_b, (float*)d_out);
}

// round 3
// speedup vs baseline: 2.2030x; 1.1898x over previous
#include <cuda_runtime.h>
#include <math.h>

#define QLEN 1024
#define BATCH 4
#define DMODEL 512
#define HEADS 8
#define DHEAD 64
#define MEMLEN 1024
#define KLEN 2048
#define DMLP 2048
#define BH 32
#define QROWS 4096
#define KROWS 8192
#define QKVW 1536
#define QSTRIDE 6144
#define QK ((size_t)QLEN * KLEN)

// ---------------- scratch ----------------
__device__ float g_qkv[KROWS * QKVW];
__device__ float g_rk[KLEN * DMODEL];
__device__ float g_qu[BH * QLEN * DHEAD];
__device__ float g_qv[BH * QLEN * DHEAD];
__device__ float g_vt[BH * DHEAD * KLEN];
__device__ float g_S[(size_t)BH * QLEN * KLEN];
__device__ float g_BD[(size_t)BH * QLEN * KLEN];
__device__ float g_attn[QROWS * DMODEL];
__device__ float g_ao[QROWS * DMODEL];
__device__ float g_y[QROWS * DMODEL];
__device__ float g_h[QROWS * DMLP];
__device__ float g_z[QROWS * DMODEL];

// ---------------- cp.async helpers ----------------
__device__ __forceinline__ void cp16(float* dst_smem, const float* src) {
    unsigned d = (unsigned)__cvta_generic_to_shared(dst_smem);
    asm volatile("cp.async.ca.shared.global [%0], [%1], 16;" :: "r"(d), "l"(src));
}
__device__ __forceinline__ void cp_commit() { asm volatile("cp.async.commit_group;"); }
__device__ __forceinline__ void cp_wait1()  { asm volatile("cp.async.wait_group 1;"); }
__device__ __forceinline__ void cp_wait0()  { asm volatile("cp.async.wait_group 0;"); }

// ---------------- tf32 NT tile engine, 2-stage cp.async pipeline -------------
// C[BM x BN] += A[BM x K] @ B[BN x K]^T. Raw fp32 bits fed to tf32 mma
// (HW mantissa truncation; err well within 1e-3 gate). K1-K0 multiple of 16.
template<int BM, int BN, int WM, int WN, int NTH>
__device__ __forceinline__ void gemm_tile(
    const float* __restrict__ A, int lda,
    const float* __restrict__ B, int ldb,
    float* __restrict__ C, int ldc,
    int K0, int K1, const float* __restrict__ bias, int act)
{
    constexpr int WARPS_M = BM / WM;
    constexpr int MT = WM / 16;
    constexpr int NT = WN / 8;
    constexpr int LA = (BM * 4) / NTH;   // float4 chunks per thread per stage (A)
    constexpr int LB = (BN * 4) / NTH;
    __shared__ float As[2][BM][20];
    __shared__ float Bs[2][BN][20];
    const int tid = threadIdx.x;
    const int lane = tid & 31;
    const int warp = tid >> 5;
    const int wm = warp % WARPS_M;
    const int wn = warp / WARPS_M;
    const int grp = lane >> 2, tig = lane & 3;

    float acc[MT][NT][4];
    #pragma unroll
    for (int mt = 0; mt < MT; mt++)
        #pragma unroll
        for (int nt = 0; nt < NT; nt++)
            #pragma unroll
            for (int q = 0; q < 4; q++) acc[mt][nt][q] = 0.0f;

    const int nk = (K1 - K0) >> 4;

    // prefetch stage 0
    {
        #pragma unroll
        for (int l = 0; l < LA; l++) {
            int idx = l * NTH + tid;
            int r = idx >> 2, c4 = (idx & 3) << 2;
            cp16(&As[0][r][c4], A + (size_t)r * lda + K0 + c4);
        }
        #pragma unroll
        for (int l = 0; l < LB; l++) {
            int idx = l * NTH + tid;
            int r = idx >> 2, c4 = (idx & 3) << 2;
            cp16(&Bs[0][r][c4], B + (size_t)r * ldb + K0 + c4);
        }
        cp_commit();
    }

    int cur = 0;
    for (int it = 0; it < nk; it++) {
        if (it + 1 < nk) {
            int kt = K0 + (it + 1) * 16;
            #pragma unroll
            for (int l = 0; l < LA; l++) {
                int idx = l * NTH + tid;
                int r = idx >> 2, c4 = (idx & 3) << 2;
                cp16(&As[cur ^ 1][r][c4], A + (size_t)r * lda + kt + c4);
            }
            #pragma unroll
            for (int l = 0; l < LB; l++) {
                int idx = l * NTH + tid;
                int r = idx >> 2, c4 = (idx & 3) << 2;
                cp16(&Bs[cur ^ 1][r][c4], B + (size_t)r * ldb + kt + c4);
            }
            cp_commit();
            cp_wait1();
        } else {
            cp_wait0();
        }
        __syncthreads();

        #pragma unroll
        for (int ks = 0; ks < 16; ks += 8) {
            unsigned af[MT][4], bf[NT][2];
            #pragma unroll
            for (int mt = 0; mt < MT; mt++) {
                int rowb = wm * WM + mt * 16;
                af[mt][0] = __float_as_uint(As[cur][rowb + grp][ks + tig]);
                af[mt][1] = __float_as_uint(As[cur][rowb + grp + 8][ks + tig]);
                af[mt][2] = __float_as_uint(As[cur][rowb + grp][ks + tig + 4]);
                af[mt][3] = __float_as_uint(As[cur][rowb + grp + 8][ks + tig + 4]);
            }
            #pragma unroll
            for (int nt = 0; nt < NT; nt++) {
                int colb = wn * WN + nt * 8 + grp;
                bf[nt][0] = __float_as_uint(Bs[cur][colb][ks + tig]);
                bf[nt][1] = __float_as_uint(Bs[cur][colb][ks + tig + 4]);
            }
            #pragma unroll
            for (int mt = 0; mt < MT; mt++)
                #pragma unroll
                for (int nt = 0; nt < NT; nt++)
                    asm volatile(
                        "mma.sync.aligned.m16n8k8.row.col.f32.tf32.tf32.f32 "
                        "{%0,%1,%2,%3}, {%4,%5,%6,%7}, {%8,%9}, {%0,%1,%2,%3};"
                        : "+f"(acc[mt][nt][0]), "+f"(acc[mt][nt][1]),
                          "+f"(acc[mt][nt][2]), "+f"(acc[mt][nt][3])
                        : "r"(af[mt][0]), "r"(af[mt][1]), "r"(af[mt][2]), "r"(af[mt][3]),
                          "r"(bf[nt][0]), "r"(bf[nt][1]));
        }
        __syncthreads();
        cur ^= 1;
    }

    #pragma unroll
    for (int mt = 0; mt < MT; mt++) {
        int r0 = wm * WM + mt * 16 + grp;
        #pragma unroll
        for (int nt = 0; nt < NT; nt++) {
            int c0 = wn * WN + nt * 8 + tig * 2;
            float v0 = acc[mt][nt][0], v1 = acc[mt][nt][1];
            float v2 = acc[mt][nt][2], v3 = acc[mt][nt][3];
            if (act >= 1) {
                float b0 = bias[c0], b1 = bias[c0 + 1];
                v0 += b0; v1 += b1; v2 += b0; v3 += b1;
            }
            if (act == 2) {
                v0 = fmaxf(v0, 0.f); v1 = fmaxf(v1, 0.f);
                v2 = fmaxf(v2, 0.f); v3 = fmaxf(v3, 0.f);
            }
            *(float2*)(C + (size_t)r0 * ldc + c0) = make_float2(v0, v1);
            *(float2*)(C + (size_t)(r0 + 8) * ldc + c0) = make_float2(v2, v3);
        }
    }
}

// ---------------- linear GEMM ----------------
__global__ __launch_bounds__(256, 2) void lin_gemm(
    const float* __restrict__ A, const float* __restrict__ W,
    const float* __restrict__ bias, float* __restrict__ C,
    int K, int N, int act)
{
    int m0 = blockIdx.y * 128, n0 = blockIdx.x * 128;
    gemm_tile<128, 128, 32, 64, 256>(A + (size_t)m0 * K, K,
                                     W + (size_t)n0 * K, K,
                                     C + (size_t)m0 * N + n0, N,
                                     0, K, bias ? bias + n0 : nullptr, act);
}

// ---------------- batched score GEMM (AC mode 0 / BD mode 1) -----------------
__global__ __launch_bounds__(256, 2) void score_gemm(
    const float* __restrict__ Q, const float* __restrict__ Bbase,
    float* __restrict__ Out, int mode)
{
    int bh = blockIdx.z, b = bh >> 3, h = bh & 7;
    int i0 = blockIdx.y * 128, j0 = blockIdx.x * 128;
    if (mode == 0) { if (j0 - i0 > 1024) return; }
    else           { if (j0 + i0 < 896) return; }
    const float* A = Q + ((size_t)bh * QLEN + i0) * DHEAD;
    const float* Bp;
    int ldb;
    if (mode == 0) {
        Bp = Bbase + (size_t)j0 * QSTRIDE + b * QKVW + DMODEL + h * DHEAD;
        ldb = QSTRIDE;
    } else {
        Bp = Bbase + (size_t)j0 * DMODEL + h * DHEAD;
        ldb = DMODEL;
    }
    float* Cp = Out + (size_t)bh * QK + (size_t)i0 * KLEN + j0;
    gemm_tile<128, 128, 32, 64, 256>(A, DHEAD, Bp, ldb, Cp, KLEN, 0, DHEAD, nullptr, 0);
}

// ---------------- attention GEMM ----------------
__global__ __launch_bounds__(128) void attn_gemm(
    const float* __restrict__ P, const float* __restrict__ Vt,
    float* __restrict__ attn)
{
    int bh = blockIdx.y, b = bh >> 3, h = bh & 7;
    int i0 = blockIdx.x * 64;
    int K1 = min(KLEN, i0 + 64 + MEMLEN);
    gemm_tile<64, 64, 32, 32, 128>(P + (size_t)bh * QK + (size_t)i0 * KLEN, KLEN,
                                   Vt + (size_t)bh * DHEAD * KLEN, KLEN,
                                   attn + (size_t)i0 * (BATCH * DMODEL) + b * DMODEL + h * DHEAD,
                                   BATCH * DMODEL, 0, K1, nullptr, 0);
}

// ---------------- prep: Qu/Qv ----------------
__global__ void prep_quv(const float* __restrict__ qkv, const float* __restrict__ u,
                         const float* __restrict__ v, float* __restrict__ Qu,
                         float* __restrict__ Qv) {
    int i = blockIdx.x, b = blockIdx.y, t = threadIdx.x;
    float q = qkv[(size_t)(MEMLEN + i) * QSTRIDE + b * QKVW + t];
    int h = t >> 6, d = t & 63;
    size_t o = ((size_t)(b * HEADS + h) * QLEN + i) * DHEAD + d;
    Qu[o] = q + u[t];
    Qv[o] = q + v[t];
}

// ---------------- prep: Vt[bh][d][j] ----------------
__global__ void prep_vt(const float* __restrict__ qkv, float* __restrict__ Vt) {
    __shared__ float t[32][33];
    int bh = blockIdx.z, b = bh >> 3, h = bh & 7;
    int j0 = blockIdx.x * 32, d0 = blockIdx.y * 32;
    int tc = threadIdx.x & 31, tr = threadIdx.x >> 5;
    #pragma unroll
    for (int rr = 0; rr < 32; rr += 8)
        t[tr + rr][tc] = qkv[(size_t)(j0 + tr + rr) * QSTRIDE + b * QKVW
                             + 2 * DMODEL + h * DHEAD + d0 + tc];
    __syncthreads();
    #pragma unroll
    for (int rr = 0; rr < 32; rr += 8)
        Vt[((size_t)bh * DHEAD + d0 + tr + rr) * KLEN + j0 + tc] = t[tc][tr + rr];
}

// ---------------- softmax with rel_shift gather ----------------
__global__ void softmax_kernel(const float* __restrict__ AC, const float* __restrict__ BD,
                               float* __restrict__ P) {
    const int i = blockIdx.x, bh = blockIdx.y;
    __shared__ float s[KLEN];
    __shared__ float red[256];
    const int tid = threadIdx.x;
    const size_t rowoff = (size_t)bh * QK + (size_t)i * KLEN;
    const float* ac = AC + rowoff;
    const float* bd = BD + rowoff + (QLEN - 1 - i);
    const int jmax = i + MEMLEN;
    for (int j = tid; j < KLEN; j += 256)
        s[j] = (j <= jmax) ? (ac[j] + bd[j]) * 0.125f : -1e30f;
    __syncthreads();
    float m = -1e30f;
    for (int j = tid; j < KLEN; j += 256) m = fmaxf(m, s[j]);
    red[tid] = m; __syncthreads();
    for (int o = 128; o > 0; o >>= 1) {
        if (tid < o) red[tid] = fmaxf(red[tid], red[tid + o]);
        __syncthreads();
    }
    m = red[0]; __syncthreads();
    float sum = 0.0f;
    for (int j = tid; j < KLEN; j += 256) {
        float e = __expf(s[j] - m);
        s[j] = e;
        sum += e;
    }
    red[tid] = sum; __syncthreads();
    for (int o = 128; o > 0; o >>= 1) {
        if (tid < o) red[tid] += red[tid + o];
        __syncthreads();
    }
    const float inv = 1.0f / red[0];
    float* pout = P + rowoff;
    for (int j = tid; j < KLEN; j += 256) pout[j] = s[j] * inv;
}

// ---------------- transpose P[bh,i,j] -> out[i,j,bh] ----------------
__global__ void transpose_prob(const float* __restrict__ P, float* __restrict__ out) {
    __shared__ float t[32][33];
    const int i = blockIdx.y, j0 = blockIdx.x * 32;
    const int tid = threadIdx.x;
    const int lj = tid & 31, lb = tid >> 5;
    #pragma unroll
    for (int r = 0; r < 4; r++) {
        int bh = r * 8 + lb;
        t[lj][bh] = P[((size_t)bh * QLEN + i) * KLEN + j0 + lj];
    }
    __syncthreads();
    const int lbh = tid & 31, ljw = tid >> 5;
    #pragma unroll
    for (int r = 0; r < 4; r++) {
        int jj = r * 8 + ljw;
        out[((size_t)i * KLEN + j0 + jj) * 32 + lbh] = t[jj][lbh];
    }
}

// ---------------- residual add + layernorm ----------------
__global__ void add_ln(const float* __restrict__ x1, const float* __restrict__ x2,
                       const float* __restrict__ g, const float* __restrict__ bb,
                       float* __restrict__ out) {
    const int row = blockIdx.x;
    const int tid = threadIdx.x;
    __shared__ float red[256];
    __shared__ float red2[256];
    const float* a = x1 + (size_t)row * DMODEL;
    const float* c = x2 + (size_t)row * DMODEL;
    float v0 = a[tid] + c[tid];
    float v1 = a[tid + 256] + c[tid + 256];
    red[tid] = v0 + v1;
    red2[tid] = v0 * v0 + v1 * v1;
    __syncthreads();
    for (int o = 128; o > 0; o >>= 1) {
        if (tid < o) { red[tid] += red[tid + o]; red2[tid] += red2[tid + o]; }
        __syncthreads();
    }
    const float mu = red[0] * (1.0f / DMODEL);
    const float var = red2[0] * (1.0f / DMODEL) - mu * mu;
    const float rstd = rsqrtf(var + 1e-5f);
    float* o = out + (size_t)row * DMODEL;
    o[tid]       = (v0 - mu) * rstd * g[tid]       + bb[tid];
    o[tid + 256] = (v1 - mu) * rstd * g[tid + 256] + bb[tid + 256];
}

// ---------------- launch ----------------
extern "C" void kernel_launch(void* const* d_in, const int* in_sizes, int n_in,
                              void* d_out, int out_size) {
    const float* inputs = (const float*)d_in[0];
    const float* r      = (const float*)d_in[1];
    const float* u      = (const float*)d_in[2];
    const float* v      = (const float*)d_in[3];
    const float* mem    = (const float*)d_in[4];
    const float* Wqkv   = (const float*)d_in[6];
    const float* Wr     = (const float*)d_in[7];
    const float* Wo     = (const float*)d_in[8];
    const float* ln1_g  = (const float*)d_in[9];
    const float* ln1_b  = (const float*)d_in[10];
    const float* w1     = (const float*)d_in[11];
    const float* b1     = (const float*)d_in[12];
    const float* w2     = (const float*)d_in[13];
    const float* b2     = (const float*)d_in[14];
    const float* ln2_g  = (const float*)d_in[15];
    const float* ln2_b  = (const float*)d_in[16];

    float *qkvp, *rkp, *qup, *qvp, *vtp, *sp, *bdp, *attnp, *aop, *yp, *hp, *zp;
    cudaGetSymbolAddress((void**)&qkvp,  g_qkv);
    cudaGetSymbolAddress((void**)&rkp,   g_rk);
    cudaGetSymbolAddress((void**)&qup,   g_qu);
    cudaGetSymbolAddress((void**)&qvp,   g_qv);
    cudaGetSymbolAddress((void**)&vtp,   g_vt);
    cudaGetSymbolAddress((void**)&sp,    g_S);
    cudaGetSymbolAddress((void**)&bdp,   g_BD);
    cudaGetSymbolAddress((void**)&attnp, g_attn);
    cudaGetSymbolAddress((void**)&aop,   g_ao);
    cudaGetSymbolAddress((void**)&yp,    g_y);
    cudaGetSymbolAddress((void**)&hp,    g_h);
    cudaGetSymbolAddress((void**)&zp,    g_z);

    // qkv projection (two GEMMs; no concat copy)
    lin_gemm<<<dim3(QKVW / 128, 4096 / 128), 256>>>(mem, Wqkv, nullptr, qkvp,
                                                    DMODEL, QKVW, 0);
    lin_gemm<<<dim3(QKVW / 128, 4096 / 128), 256>>>(inputs, Wqkv, nullptr,
                                                    qkvp + (size_t)4096 * QKVW,
                                                    DMODEL, QKVW, 0);
    lin_gemm<<<dim3(DMODEL / 128, KLEN / 128), 256>>>(r, Wr, nullptr, rkp,
                                                      DMODEL, DMODEL, 0);
    prep_quv<<<dim3(QLEN, BATCH), 512>>>(qkvp, u, v, qup, qvp);
    prep_vt<<<dim3(KLEN / 32, DHEAD / 32, BH), 256>>>(qkvp, vtp);
    // scores
    score_gemm<<<dim3(KLEN / 128, QLEN / 128, BH), 256>>>(qup, qkvp, sp, 0);
    score_gemm<<<dim3(KLEN / 128, QLEN / 128, BH), 256>>>(qvp, rkp, bdp, 1);
    // softmax (in-place into S => prob [bh,i,j])
    softmax_kernel<<<dim3(QLEN, BH), 256>>>(sp, bdp, sp);
    // prob tuple output
    float* prob_out = (float*)d_out + QLEN * BATCH * DMODEL;
    transpose_prob<<<dim3(KLEN / 32, QLEN), 256>>>(sp, prob_out);
    // attn = prob @ V
    attn_gemm<<<dim3(QLEN / 64, BH), 128>>>(sp, vtp, attnp);
    lin_gemm<<<dim3(DMODEL / 128, QROWS / 128), 256>>>(attnp, Wo, nullptr, aop,
                                                       DMODEL, DMODEL, 0);
    add_ln<<<QROWS, 256>>>(inputs, aop, ln1_g, ln1_b, yp);
    lin_gemm<<<dim3(DMLP / 128, QROWS / 128), 256>>>(yp, w1, b1, hp,
                                                     DMODEL, DMLP, 2);
    lin_gemm<<<dim3(DMODEL / 128, QROWS / 128), 256>>>(hp, w2, b2, zp,
                                                       DMLP, DMODEL, 1);
    add_ln<<<QROWS, 256>>>(yp, zp, ln2_g, ln2_b, (float*)d_out);
}